// round 11
// baseline (speedup 1.0000x reference)
#include <cuda_runtime.h>
#include <cuda_bf16.h>
#include <cstdint>
#include <cstddef>

// ---------------- problem constants ----------------
#define T_LEN 128
#define BATCH 32
#define HID   1024
#define VOCAB 32000
#define MROWS (T_LEN * BATCH)        // 4096
#define LOGITS_ELEMS ((size_t)MROWS * VOCAB)   // 131072000
#define HIDDEN_ELEMS (2 * BATCH * HID)         // 65536

// ---------------- device scratch (no runtime alloc allowed) ----------------
__device__ float g_x [MROWS * HID];     // layer input / output sequence (16 MB)
__device__ float g_xw[MROWS * HID];     // precomputed input projection  (16 MB)
// hidden ping-pong, float4-quad layout: buf[q*BATCH + b] holds h[4q..4q+3][b]
__device__ float4 g_h4[2 * (HID / 4) * BATCH];
__device__ int   g_ctr;                 // persistent-kernel barrier counter

// =====================================================================
// Embedding gather
// =====================================================================
__global__ __launch_bounds__(256)
void embed_k(const int* __restrict__ idx, const float* __restrict__ emb,
             float* __restrict__ xout)
{
    int row = blockIdx.x;
    int tok = idx[row];
    const float4* s = (const float4*)(emb + (size_t)tok * HID);
    float4* d = (float4*)(xout + (size_t)row * HID);
    d[threadIdx.x] = s[threadIdx.x];
}

// =====================================================================
// tf32 helpers
// =====================================================================
__device__ __forceinline__ float tf32_hi(float v)
{
    uint32_t t;
    asm("cvt.rna.tf32.f32 %0, %1;" : "=r"(t) : "f"(v));
    return __uint_as_float(t);
}
__device__ __forceinline__ void split_cvt(float v, float& hi, float& lo)
{
    hi = tf32_hi(v);
    lo = tf32_hi(v - hi);
}

__device__ __forceinline__ void mma_tf32(float c[4], uint32_t a0, uint32_t a1,
                                         uint32_t a2, uint32_t a3,
                                         uint32_t b0, uint32_t b1)
{
    asm volatile(
        "mma.sync.aligned.m16n8k8.row.col.f32.tf32.tf32.f32 "
        "{%0,%1,%2,%3}, {%4,%5,%6,%7}, {%8,%9}, {%0,%1,%2,%3};"
        : "+f"(c[0]), "+f"(c[1]), "+f"(c[2]), "+f"(c[3])
        : "r"(a0), "r"(a1), "r"(a2), "r"(a3), "r"(b0), "r"(b1));
}

__device__ __forceinline__ void cp16(uint32_t dst, const void* src)
{
    asm volatile("cp.async.cg.shared.global [%0], [%1], 16;" :: "r"(dst), "l"(src));
}

#define BM 128
#define BN 128
#define BK 32
#define SAPAD 132

// =====================================================================
// Output projection GEMM v2: C = A[M,K] * B[N,K]^T + bias.
// 128 threads, 4 warps in 2x2, warp tile 64x64 (LDS/MMA ratio 1.0).
// cp.async double-buffered, raw f32 operands (HMMA.tf32 truncates in HW).
// Smem tiles [row][36] (conflict-free fragment LDS), 2 blocks/SM, 72 KB.
// =====================================================================
#define OSTR 36
#define OTILE (BM * OSTR)

__global__ __launch_bounds__(128, 2)
void gemm_tf32(const float* __restrict__ A, const float* __restrict__ B,
               float* __restrict__ C, const float* __restrict__ bias,
               int M, int N, int K)
{
    extern __shared__ float smem[];
    // layout: A0 | A1 | B0 | B1, each OTILE floats

    int tid  = threadIdx.x;
    int warp = tid >> 5, lane = tid & 31;
    int wm   = warp >> 1;          // 0..1 (64-row slab)
    int wn   = warp & 1;           // 0..1 (64-col slab)
    int gID  = lane >> 2;          // 0..7
    int tig  = lane & 3;           // 0..3

    int rowBase = blockIdx.x * BM;
    int colBase = blockIdx.y * BN;

    // staging: thread -> one tile row (128B = 8 x 16B) for A and B
    const float* Asrc = A + (size_t)(rowBase + tid) * K;
    const float* Bsrc = B + (size_t)(colBase + tid) * K;
    uint32_t smemBase = (uint32_t)__cvta_generic_to_shared(smem);
    uint32_t aDst = smemBase + (uint32_t)(tid * OSTR) * 4;
    uint32_t bDst = aDst + 2 * OTILE * 4;

    const int NT = K / BK;

    float acc[4][8][4];
#pragma unroll
    for (int mt = 0; mt < 4; mt++)
#pragma unroll
        for (int nt = 0; nt < 8; nt++)
#pragma unroll
            for (int q = 0; q < 4; q++) acc[mt][nt][q] = 0.f;

    // prologue: stage tile 0 into buffer 0
#pragma unroll
    for (int c = 0; c < 8; c++) {
        cp16(aDst + c * 16, Asrc + c * 4);
        cp16(bDst + c * 16, Bsrc + c * 4);
    }
    asm volatile("cp.async.commit_group;");

    for (int kt = 0; kt < NT; kt++) {
        int cur = kt & 1;
        if (kt + 1 < NT) {
            int nxt = cur ^ 1;
            const float* ap = Asrc + (size_t)(kt + 1) * BK;
            const float* bp = Bsrc + (size_t)(kt + 1) * BK;
            uint32_t ad = aDst + (uint32_t)nxt * OTILE * 4;
            uint32_t bd = bDst + (uint32_t)nxt * OTILE * 4;
#pragma unroll
            for (int c = 0; c < 8; c++) {
                cp16(ad + c * 16, ap + c * 4);
                cp16(bd + c * 16, bp + c * 4);
            }
            asm volatile("cp.async.commit_group;");
            asm volatile("cp.async.wait_group 1;");
        } else {
            asm volatile("cp.async.wait_group 0;");
        }
        __syncthreads();

        const float* sA = smem + cur * OTILE;
        const float* sB = smem + 2 * OTILE + cur * OTILE;

#pragma unroll
        for (int ks = 0; ks < 4; ks++) {
            int kb = ks * 8;
            uint32_t af[4][4];
#pragma unroll
            for (int mt = 0; mt < 4; mt++) {
                int m0 = wm * 64 + mt * 16 + gID;
                af[mt][0] = __float_as_uint(sA[(m0    ) * OSTR + kb + tig    ]);
                af[mt][1] = __float_as_uint(sA[(m0 + 8) * OSTR + kb + tig    ]);
                af[mt][2] = __float_as_uint(sA[(m0    ) * OSTR + kb + tig + 4]);
                af[mt][3] = __float_as_uint(sA[(m0 + 8) * OSTR + kb + tig + 4]);
            }
#pragma unroll
            for (int nt = 0; nt < 8; nt++) {
                int n0 = wn * 64 + nt * 8 + gID;
                uint32_t b0 = __float_as_uint(sB[n0 * OSTR + kb + tig    ]);
                uint32_t b1 = __float_as_uint(sB[n0 * OSTR + kb + tig + 4]);
#pragma unroll
                for (int mt = 0; mt < 4; mt++)
                    mma_tf32(acc[mt][nt], af[mt][0], af[mt][1], af[mt][2],
                             af[mt][3], b0, b1);
            }
        }
        __syncthreads();
    }

#pragma unroll
    for (int mt = 0; mt < 4; mt++) {
#pragma unroll
        for (int nt = 0; nt < 8; nt++) {
            int r0 = rowBase + wm * 64 + mt * 16 + gID;
            int c0 = colBase + wn * 64 + nt * 8 + tig * 2;
            float bi0 = bias ? bias[c0] : 0.f;
            float bi1 = bias ? bias[c0 + 1] : 0.f;
            float* p0 = C + (size_t)r0 * N + c0;
            float* p1 = C + (size_t)(r0 + 8) * N + c0;
            *(float2*)p0 = make_float2(acc[mt][nt][0] + bi0, acc[mt][nt][1] + bi1);
            *(float2*)p1 = make_float2(acc[mt][nt][2] + bi0, acc[mt][nt][3] + bi1);
        }
    }
}

// =====================================================================
// Fused 3-term tf32 split GEMM (near-fp32): C = A*B^T + bias in ONE pass.
// (input projections feed the 128-step recurrence -> keep rna split)
// =====================================================================
__global__ __launch_bounds__(256)
void gemm_split3(const float* __restrict__ A, const float* __restrict__ B,
                 float* __restrict__ C, const float* __restrict__ bias,
                 int M, int N, int K)
{
    extern __shared__ float smem[];
    float* Ah = smem;
    float* Al = smem + BK * SAPAD;
    float* Bh = smem + 2 * BK * SAPAD;
    float* Bl = smem + 3 * BK * SAPAD;

    int tid  = threadIdx.x;
    int warp = tid >> 5, lane = tid & 31;
    int wm   = warp >> 2;
    int wn   = warp & 3;
    int gID  = lane >> 2;
    int tig  = lane & 3;

    int rowBase = blockIdx.x * BM;
    int colBase = blockIdx.y * BN;

    int lc4 = tid & 7;
    int lr  = tid >> 3;
    const float* Aload = A + (size_t)(rowBase + lr) * K + lc4 * 4;
    const float* Bload = B + (size_t)(colBase + lr) * K + lc4 * 4;

    float acc[4][4][4];
#pragma unroll
    for (int mt = 0; mt < 4; mt++)
#pragma unroll
        for (int nt = 0; nt < 4; nt++)
#pragma unroll
            for (int q = 0; q < 4; q++) acc[mt][nt][q] = 0.f;

    const int NT = K / BK;

    for (int kt = 0; kt < NT; kt++) {
#pragma unroll
        for (int i = 0; i < 4; i++) {
            float4 va = *(const float4*)(Aload + (size_t)kt * BK + (size_t)i * 32 * K);
            float4 vb = *(const float4*)(Bload + (size_t)kt * BK + (size_t)i * 32 * K);
            int m = lr + i * 32;
            float a4[4] = {va.x, va.y, va.z, va.w};
            float b4[4] = {vb.x, vb.y, vb.z, vb.w};
#pragma unroll
            for (int q = 0; q < 4; q++) {
                float hi, lo;
                split_cvt(a4[q], hi, lo);
                Ah[(lc4 * 4 + q) * SAPAD + m] = hi;
                Al[(lc4 * 4 + q) * SAPAD + m] = lo;
                split_cvt(b4[q], hi, lo);
                Bh[(lc4 * 4 + q) * SAPAD + m] = hi;
                Bl[(lc4 * 4 + q) * SAPAD + m] = lo;
            }
        }
        __syncthreads();

#pragma unroll
        for (int ks = 0; ks < 4; ks++) {
            int kb = ks * 8;
            uint32_t ah[4][4], al[4][4];
#pragma unroll
            for (int mt = 0; mt < 4; mt++) {
                int m0 = wm * 64 + mt * 16 + gID;
                ah[mt][0] = __float_as_uint(Ah[(kb + tig    ) * SAPAD + m0    ]);
                ah[mt][1] = __float_as_uint(Ah[(kb + tig    ) * SAPAD + m0 + 8]);
                ah[mt][2] = __float_as_uint(Ah[(kb + tig + 4) * SAPAD + m0    ]);
                ah[mt][3] = __float_as_uint(Ah[(kb + tig + 4) * SAPAD + m0 + 8]);
                al[mt][0] = __float_as_uint(Al[(kb + tig    ) * SAPAD + m0    ]);
                al[mt][1] = __float_as_uint(Al[(kb + tig    ) * SAPAD + m0 + 8]);
                al[mt][2] = __float_as_uint(Al[(kb + tig + 4) * SAPAD + m0    ]);
                al[mt][3] = __float_as_uint(Al[(kb + tig + 4) * SAPAD + m0 + 8]);
            }
#pragma unroll
            for (int nt = 0; nt < 4; nt++) {
                int n0 = wn * 32 + nt * 8 + gID;
                uint32_t bh0 = __float_as_uint(Bh[(kb + tig    ) * SAPAD + n0]);
                uint32_t bh1 = __float_as_uint(Bh[(kb + tig + 4) * SAPAD + n0]);
                uint32_t bl0 = __float_as_uint(Bl[(kb + tig    ) * SAPAD + n0]);
                uint32_t bl1 = __float_as_uint(Bl[(kb + tig + 4) * SAPAD + n0]);
#pragma unroll
                for (int mt = 0; mt < 4; mt++) {
                    mma_tf32(acc[mt][nt], ah[mt][0], ah[mt][1], ah[mt][2], ah[mt][3], bh0, bh1);
                    mma_tf32(acc[mt][nt], al[mt][0], al[mt][1], al[mt][2], al[mt][3], bh0, bh1);
                    mma_tf32(acc[mt][nt], ah[mt][0], ah[mt][1], ah[mt][2], ah[mt][3], bl0, bl1);
                }
            }
        }
        __syncthreads();
    }

#pragma unroll
    for (int mt = 0; mt < 4; mt++) {
#pragma unroll
        for (int nt = 0; nt < 4; nt++) {
            int r0 = rowBase + wm * 64 + mt * 16 + gID;
            int c0 = colBase + wn * 32 + nt * 8 + tig * 2;
            float bi0 = bias ? bias[c0] : 0.f;
            float bi1 = bias ? bias[c0 + 1] : 0.f;
            float* p0 = C + (size_t)r0 * N + c0;
            float* p1 = C + (size_t)(r0 + 8) * N + c0;
            *(float2*)p0 = make_float2(acc[mt][nt][0] + bi0, acc[mt][nt][1] + bi1);
            *(float2*)p1 = make_float2(acc[mt][nt][2] + bi0, acc[mt][nt][3] + bi1);
        }
    }
}

// =====================================================================
// Persistent RNN recurrence v4: 512 threads (16 warps, 4/SMSP) to hide
// LDS/LDG latency; warp owns a 64-k slice. Barrier unchanged (proven R9).
// =====================================================================
__device__ __forceinline__ void red_add_release_gpu(int* p, int v)
{
    asm volatile("red.release.gpu.global.add.s32 [%0], %1;" :: "l"(p), "r"(v) : "memory");
}
__device__ __forceinline__ int ld_acquire_int(const int* p)
{
    int v;
    asm volatile("ld.acquire.gpu.global.s32 %0, [%1];" : "=r"(v) : "l"(p) : "memory");
    return v;
}

// transpose hidden[l] [B][H] -> g_h4 buf0 quad layout; reset barrier counter
__global__ __launch_bounds__(256)
void htrans_in_k(const float* __restrict__ hsrc)
{
    if (blockIdx.x == 0 && threadIdx.x == 0) g_ctr = 0;
    int idx = blockIdx.x * 256 + threadIdx.x;   // over 8192 quads
    int q = idx >> 5;          // 0..255  (k-quad)
    int b = idx & 31;
    float4 v = make_float4(hsrc[(size_t)b * HID + q * 4 + 0],
                           hsrc[(size_t)b * HID + q * 4 + 1],
                           hsrc[(size_t)b * HID + q * 4 + 2],
                           hsrc[(size_t)b * HID + q * 4 + 3]);
    g_h4[(size_t)q * BATCH + b] = v;
}

__global__ __launch_bounds__(512)
void rnn_persist(const float* __restrict__ xw,   // [128][32][1024]
                 const float* __restrict__ Whh,  // [1024][1024]
                 const float* __restrict__ bhh,  // [1024]
                 float* __restrict__ yseq)       // [128][32][1024]
{
    __shared__ float swT[HID][8];        // 32 KB: swT[k][j] = Whh[jbase+j][k]
    __shared__ float sb[8];
    __shared__ float red[16][BATCH][8];  // 16 KB partials

    int tid = threadIdx.x;
    int bid = blockIdx.x;
    int jbase = bid * 8;

    // load W slice transposed (coalesced gmem reads)
    for (int idx = tid; idx < 8 * HID; idx += 512) {
        int j = idx >> 10;
        int k = idx & 1023;
        swT[k][j] = Whh[(size_t)(jbase + j) * HID + k];
    }
    if (tid < 8) sb[tid] = bhh[jbase + tid];
    __syncthreads();

    int w    = tid >> 5;        // warp 0..15 -> 64-k slice
    int lane = tid & 31;        // lane -> batch
    int kqbase = w * 16;        // 16 quads (=64 k) per warp
    int rb = (tid >> 3) & 31;   // reduce: batch (threads 0..255)
    int rj = tid & 7;           // reduce: local j
    int jout = jbase + rj;
    int houtOff = ((jout >> 2) * BATCH + rb) * 4 + (jout & 3);

#pragma unroll 1
    for (int t = 0; t < T_LEN; t++) {
        const float4* hcur = g_h4 + (size_t)(t & 1) * (HID / 4) * BATCH;
        float*        hnxt = (float*)(g_h4 + (size_t)((t + 1) & 1) * (HID / 4) * BATCH);

        float xval = 0.f;
        if (tid < 256)
            xval = xw[(size_t)t * BATCH * HID + (size_t)rb * HID + jout];

        float acc[8];
#pragma unroll
        for (int j = 0; j < 8; j++) acc[j] = 0.f;

        float4 hv[8], hp[8];
#pragma unroll
        for (int i = 0; i < 8; i++)
            hv[i] = __ldcg(hcur + (size_t)(kqbase + i) * BATCH + lane);

#pragma unroll
        for (int c = 0; c < 2; c++) {
            if (c < 1) {
#pragma unroll
                for (int i = 0; i < 8; i++)
                    hp[i] = __ldcg(hcur + (size_t)(kqbase + 8 + i) * BATCH + lane);
            }
#pragma unroll
            for (int i = 0; i < 8; i++) {
                int k0 = (kqbase + c * 8 + i) * 4;
                float hd[4] = {hv[i].x, hv[i].y, hv[i].z, hv[i].w};
#pragma unroll
                for (int d = 0; d < 4; d++) {
                    float4 wa = *(const float4*)&swT[k0 + d][0];
                    float4 wb = *(const float4*)&swT[k0 + d][4];
                    acc[0] += wa.x * hd[d];
                    acc[1] += wa.y * hd[d];
                    acc[2] += wa.z * hd[d];
                    acc[3] += wa.w * hd[d];
                    acc[4] += wb.x * hd[d];
                    acc[5] += wb.y * hd[d];
                    acc[6] += wb.z * hd[d];
                    acc[7] += wb.w * hd[d];
                }
            }
            if (c < 1) {
#pragma unroll
                for (int i = 0; i < 8; i++) hv[i] = hp[i];
            }
        }

        // cross-warp (k-slice) reduction over 16 warps
        *(float4*)&red[w][lane][0] = make_float4(acc[0], acc[1], acc[2], acc[3]);
        *(float4*)&red[w][lane][4] = make_float4(acc[4], acc[5], acc[6], acc[7]);
        __syncthreads();
        if (tid < 256) {
            float s = 0.f;
#pragma unroll
            for (int ww = 0; ww < 16; ww++) s += red[ww][rb][rj];
            float v = tanhf(s + sb[rj] + xval);
            __stcg(hnxt + houtOff, v);
            yseq[(size_t)t * BATCH * HID + (size_t)rb * HID + jout] = v;
        }

        // grid barrier (single release-add + single acquire poller + sleep)
        __syncthreads();
        if (tid == 0) {
            red_add_release_gpu(&g_ctr, 1);
            int target = 128 * (t + 1);
            while (ld_acquire_int(&g_ctr) < target) {
                __nanosleep(64);
            }
        }
        __syncthreads();
    }
}

// =====================================================================
// In-place log_softmax over rows of 32000. Row cached in 128 KB smem.
// =====================================================================
__global__ __launch_bounds__(256)
void logsoftmax_k(float* __restrict__ out)
{
    extern __shared__ float srow[];
    __shared__ float red[256];
    int tid = threadIdx.x;
    float4* p4 = (float4*)(out + (size_t)blockIdx.x * VOCAB);

    float m = -3.4e38f;
#pragma unroll 4
    for (int i = tid; i < VOCAB / 4; i += 256) {
        float4 v = p4[i];
        *(float4*)&srow[i * 4] = v;
        m = fmaxf(m, fmaxf(fmaxf(v.x, v.y), fmaxf(v.z, v.w)));
    }
    red[tid] = m; __syncthreads();
    for (int s = 128; s > 0; s >>= 1) {
        if (tid < s) red[tid] = fmaxf(red[tid], red[tid + s]);
        __syncthreads();
    }
    float rm = red[0]; __syncthreads();

    float sum = 0.f;
    for (int i = tid; i < VOCAB; i += 256) sum += expf(srow[i] - rm);
    red[tid] = sum; __syncthreads();
    for (int s = 128; s > 0; s >>= 1) {
        if (tid < s) red[tid] += red[tid + s];
        __syncthreads();
    }
    float lz = rm + logf(red[0]);

    for (int i = tid; i < VOCAB / 4; i += 256) {
        float4 v = *(float4*)&srow[i * 4];
        v.x -= lz; v.y -= lz; v.z -= lz; v.w -= lz;
        p4[i] = v;
    }
}

// =====================================================================
// host orchestration (graph-capturable)
// =====================================================================
extern "C" void kernel_launch(void* const* d_in, const int* in_sizes, int n_in,
                              void* d_out, int out_size)
{
    const int*   input_x = (const int*)  d_in[0];
    const float* hidden  = (const float*)d_in[1];
    const float* emb     = (const float*)d_in[2];
    const float* W_ih    = (const float*)d_in[3];
    const float* W_hh    = (const float*)d_in[4];
    const float* b_ih    = (const float*)d_in[5];
    const float* b_hh    = (const float*)d_in[6];
    const float* W_out   = (const float*)d_in[7];
    const float* b_out   = (const float*)d_in[8];
    float* out = (float*)d_out;

    float *gx, *gxw;
    cudaGetSymbolAddress((void**)&gx,  g_x);
    cudaGetSymbolAddress((void**)&gxw, g_xw);

    cudaFuncSetAttribute(logsoftmax_k,
                         cudaFuncAttributeMaxDynamicSharedMemorySize,
                         VOCAB * (int)sizeof(float));
    cudaFuncSetAttribute(gemm_split3,
                         cudaFuncAttributeMaxDynamicSharedMemorySize,
                         4 * BK * SAPAD * (int)sizeof(float));
    cudaFuncSetAttribute(gemm_tf32,
                         cudaFuncAttributeMaxDynamicSharedMemorySize,
                         4 * OTILE * (int)sizeof(float));

    const int writeHidden = (size_t)out_size >= LOGITS_ELEMS + HIDDEN_ELEMS;

    // 1) embedding gather
    embed_k<<<MROWS, 256>>>(input_x, emb, gx);

    for (int l = 0; l < 2; l++) {
        const float* Wi = W_ih + (size_t)l * HID * HID;
        const float* Wh = W_hh + (size_t)l * HID * HID;
        const float* bi = b_ih + (size_t)l * HID;
        const float* bh = b_hh + (size_t)l * HID;

        // init transposed hidden (buf 0) + reset barrier counter
        htrans_in_k<<<BATCH * HID / 256, 256>>>(hidden + (size_t)l * BATCH * HID);

        // input projection: fused 3-term tf32 split, single launch
        dim3 gp(MROWS / BM, HID / BN);
        gemm_split3<<<gp, 256, 4 * BK * SAPAD * (int)sizeof(float)>>>(
            gx, Wi, gxw, bi, MROWS, HID, HID);

        // persistent recurrence (exact fp32), 512 threads
        rnn_persist<<<128, 512>>>(gxw, Wh, bh, gx);

        // new_hidden[l] = y[T-1]
        if (writeHidden)
            cudaMemcpyAsync(out + LOGITS_ELEMS + (size_t)l * BATCH * HID,
                            gx + (size_t)(T_LEN - 1) * BATCH * HID,
                            (size_t)BATCH * HID * sizeof(float),
                            cudaMemcpyDeviceToDevice, 0);
    }

    // output projection (cp.async double-buffered HMMA tf32, 64x64 warp tiles)
    dim3 go(MROWS / BM, VOCAB / BN);
    gemm_tf32<<<go, 128, 4 * OTILE * (int)sizeof(float)>>>(
        gx, W_out, out, b_out, MROWS, VOCAB, HID);

    // in-place log_softmax
    logsoftmax_k<<<MROWS, 256, VOCAB * (int)sizeof(float)>>>(out);
}

// round 12
// speedup vs baseline: 1.0864x; 1.0864x over previous
#include <cuda_runtime.h>
#include <cuda_bf16.h>
#include <cstdint>
#include <cstddef>

// ---------------- problem constants ----------------
#define T_LEN 128
#define BATCH 32
#define HID   1024
#define VOCAB 32000
#define MROWS (T_LEN * BATCH)        // 4096
#define LOGITS_ELEMS ((size_t)MROWS * VOCAB)   // 131072000
#define HIDDEN_ELEMS (2 * BATCH * HID)         // 65536

// ---------------- device scratch (no runtime alloc allowed) ----------------
__device__ float g_x [MROWS * HID];     // layer input / output sequence (16 MB)
__device__ float g_xw[MROWS * HID];     // precomputed input projection  (16 MB)
// hidden ping-pong, float4-quad layout: buf[q*BATCH + b] holds h[4q..4q+3][b]
__device__ float4 g_h4[2 * (HID / 4) * BATCH];
__device__ int   g_ctr;                 // persistent-kernel barrier counter

// =====================================================================
// Embedding gather
// =====================================================================
__global__ __launch_bounds__(256)
void embed_k(const int* __restrict__ idx, const float* __restrict__ emb,
             float* __restrict__ xout)
{
    int row = blockIdx.x;
    int tok = idx[row];
    const float4* s = (const float4*)(emb + (size_t)tok * HID);
    float4* d = (float4*)(xout + (size_t)row * HID);
    d[threadIdx.x] = s[threadIdx.x];
}

// =====================================================================
// tf32 helpers
// =====================================================================
__device__ __forceinline__ float tf32_hi(float v)
{
    uint32_t t;
    asm("cvt.rna.tf32.f32 %0, %1;" : "=r"(t) : "f"(v));
    return __uint_as_float(t);
}
__device__ __forceinline__ void split_cvt(float v, float& hi, float& lo)
{
    hi = tf32_hi(v);
    lo = tf32_hi(v - hi);
}

__device__ __forceinline__ void mma_tf32(float c[4], uint32_t a0, uint32_t a1,
                                         uint32_t a2, uint32_t a3,
                                         uint32_t b0, uint32_t b1)
{
    asm volatile(
        "mma.sync.aligned.m16n8k8.row.col.f32.tf32.tf32.f32 "
        "{%0,%1,%2,%3}, {%4,%5,%6,%7}, {%8,%9}, {%0,%1,%2,%3};"
        : "+f"(c[0]), "+f"(c[1]), "+f"(c[2]), "+f"(c[3])
        : "r"(a0), "r"(a1), "r"(a2), "r"(a3), "r"(b0), "r"(b1));
}

__device__ __forceinline__ void cp16(uint32_t dst, const void* src)
{
    asm volatile("cp.async.cg.shared.global [%0], [%1], 16;" :: "r"(dst), "l"(src));
}

#define BM 128
#define BN 128
#define BK 32
#define SAPAD 132

// =====================================================================
// Output projection GEMM (R10 proven version): C = A[M,K]*B[N,K]^T + bias.
// 256 threads, 8 warps 2x4, warp tile 64x32.
// cp.async double-buffered, raw f32 operands (HMMA.tf32 truncates in HW).
// Smem tiles [row][36] (conflict-free fragment LDS), 2 blocks/SM, 72 KB.
// =====================================================================
#define OSTR 36
#define OTILE (BM * OSTR)

__global__ __launch_bounds__(256, 2)
void gemm_tf32(const float* __restrict__ A, const float* __restrict__ B,
               float* __restrict__ C, const float* __restrict__ bias,
               int M, int N, int K)
{
    extern __shared__ float smem[];
    // layout: A0 | A1 | B0 | B1, each OTILE floats

    int tid  = threadIdx.x;
    int warp = tid >> 5, lane = tid & 31;
    int wm   = warp >> 2;
    int wn   = warp & 3;
    int gID  = lane >> 2;
    int tig  = lane & 3;

    int rowBase = blockIdx.x * BM;
    int colBase = blockIdx.y * BN;

    // stage mapping: 2 threads per tile row, each 64B (4 x 16B)
    int srow = tid >> 1;        // 0..127
    int shalf = tid & 1;        // 0..1 (16-float half of BK)
    const float* Asrc = A + (size_t)(rowBase + srow) * K + shalf * 16;
    const float* Bsrc = B + (size_t)(colBase + srow) * K + shalf * 16;
    uint32_t smemBase = (uint32_t)__cvta_generic_to_shared(smem);
    uint32_t aDst = smemBase + (uint32_t)(srow * OSTR + shalf * 16) * 4;
    uint32_t bDst = aDst + 2 * OTILE * 4;

    const int NT = K / BK;

    float acc[4][4][4];
#pragma unroll
    for (int mt = 0; mt < 4; mt++)
#pragma unroll
        for (int nt = 0; nt < 4; nt++)
#pragma unroll
            for (int q = 0; q < 4; q++) acc[mt][nt][q] = 0.f;

    // prologue: stage tile 0 into buffer 0
#pragma unroll
    for (int c = 0; c < 4; c++) {
        cp16(aDst + c * 16, Asrc + c * 4);
        cp16(bDst + c * 16, Bsrc + c * 4);
    }
    asm volatile("cp.async.commit_group;");

    for (int kt = 0; kt < NT; kt++) {
        int cur = kt & 1;
        if (kt + 1 < NT) {
            int nxt = cur ^ 1;
            const float* ap = Asrc + (size_t)(kt + 1) * BK;
            const float* bp = Bsrc + (size_t)(kt + 1) * BK;
            uint32_t ad = aDst + (uint32_t)nxt * OTILE * 4;
            uint32_t bd = bDst + (uint32_t)nxt * OTILE * 4;
#pragma unroll
            for (int c = 0; c < 4; c++) {
                cp16(ad + c * 16, ap + c * 4);
                cp16(bd + c * 16, bp + c * 4);
            }
            asm volatile("cp.async.commit_group;");
            asm volatile("cp.async.wait_group 1;");
        } else {
            asm volatile("cp.async.wait_group 0;");
        }
        __syncthreads();

        const float* sA = smem + cur * OTILE;
        const float* sB = smem + 2 * OTILE + cur * OTILE;

#pragma unroll
        for (int ks = 0; ks < 4; ks++) {
            int kb = ks * 8;
            uint32_t af[4][4];
#pragma unroll
            for (int mt = 0; mt < 4; mt++) {
                int m0 = wm * 64 + mt * 16 + gID;
                af[mt][0] = __float_as_uint(sA[(m0    ) * OSTR + kb + tig    ]);
                af[mt][1] = __float_as_uint(sA[(m0 + 8) * OSTR + kb + tig    ]);
                af[mt][2] = __float_as_uint(sA[(m0    ) * OSTR + kb + tig + 4]);
                af[mt][3] = __float_as_uint(sA[(m0 + 8) * OSTR + kb + tig + 4]);
            }
#pragma unroll
            for (int nt = 0; nt < 4; nt++) {
                int n0 = wn * 32 + nt * 8 + gID;
                uint32_t b0 = __float_as_uint(sB[n0 * OSTR + kb + tig    ]);
                uint32_t b1 = __float_as_uint(sB[n0 * OSTR + kb + tig + 4]);
#pragma unroll
                for (int mt = 0; mt < 4; mt++)
                    mma_tf32(acc[mt][nt], af[mt][0], af[mt][1], af[mt][2],
                             af[mt][3], b0, b1);
            }
        }
        __syncthreads();
    }

#pragma unroll
    for (int mt = 0; mt < 4; mt++) {
#pragma unroll
        for (int nt = 0; nt < 4; nt++) {
            int r0 = rowBase + wm * 64 + mt * 16 + gID;
            int c0 = colBase + wn * 32 + nt * 8 + tig * 2;
            float bi0 = bias ? bias[c0] : 0.f;
            float bi1 = bias ? bias[c0 + 1] : 0.f;
            float* p0 = C + (size_t)r0 * N + c0;
            float* p1 = C + (size_t)(r0 + 8) * N + c0;
            *(float2*)p0 = make_float2(acc[mt][nt][0] + bi0, acc[mt][nt][1] + bi1);
            *(float2*)p1 = make_float2(acc[mt][nt][2] + bi0, acc[mt][nt][3] + bi1);
        }
    }
}

// =====================================================================
// Fused 3-term tf32 split GEMM (near-fp32): C = A*B^T + bias in ONE pass.
// (input projections feed the 128-step recurrence -> keep rna split)
// =====================================================================
__global__ __launch_bounds__(256)
void gemm_split3(const float* __restrict__ A, const float* __restrict__ B,
                 float* __restrict__ C, const float* __restrict__ bias,
                 int M, int N, int K)
{
    extern __shared__ float smem[];
    float* Ah = smem;
    float* Al = smem + BK * SAPAD;
    float* Bh = smem + 2 * BK * SAPAD;
    float* Bl = smem + 3 * BK * SAPAD;

    int tid  = threadIdx.x;
    int warp = tid >> 5, lane = tid & 31;
    int wm   = warp >> 2;
    int wn   = warp & 3;
    int gID  = lane >> 2;
    int tig  = lane & 3;

    int rowBase = blockIdx.x * BM;
    int colBase = blockIdx.y * BN;

    int lc4 = tid & 7;
    int lr  = tid >> 3;
    const float* Aload = A + (size_t)(rowBase + lr) * K + lc4 * 4;
    const float* Bload = B + (size_t)(colBase + lr) * K + lc4 * 4;

    float acc[4][4][4];
#pragma unroll
    for (int mt = 0; mt < 4; mt++)
#pragma unroll
        for (int nt = 0; nt < 4; nt++)
#pragma unroll
            for (int q = 0; q < 4; q++) acc[mt][nt][q] = 0.f;

    const int NT = K / BK;

    for (int kt = 0; kt < NT; kt++) {
#pragma unroll
        for (int i = 0; i < 4; i++) {
            float4 va = *(const float4*)(Aload + (size_t)kt * BK + (size_t)i * 32 * K);
            float4 vb = *(const float4*)(Bload + (size_t)kt * BK + (size_t)i * 32 * K);
            int m = lr + i * 32;
            float a4[4] = {va.x, va.y, va.z, va.w};
            float b4[4] = {vb.x, vb.y, vb.z, vb.w};
#pragma unroll
            for (int q = 0; q < 4; q++) {
                float hi, lo;
                split_cvt(a4[q], hi, lo);
                Ah[(lc4 * 4 + q) * SAPAD + m] = hi;
                Al[(lc4 * 4 + q) * SAPAD + m] = lo;
                split_cvt(b4[q], hi, lo);
                Bh[(lc4 * 4 + q) * SAPAD + m] = hi;
                Bl[(lc4 * 4 + q) * SAPAD + m] = lo;
            }
        }
        __syncthreads();

#pragma unroll
        for (int ks = 0; ks < 4; ks++) {
            int kb = ks * 8;
            uint32_t ah[4][4], al[4][4];
#pragma unroll
            for (int mt = 0; mt < 4; mt++) {
                int m0 = wm * 64 + mt * 16 + gID;
                ah[mt][0] = __float_as_uint(Ah[(kb + tig    ) * SAPAD + m0    ]);
                ah[mt][1] = __float_as_uint(Ah[(kb + tig    ) * SAPAD + m0 + 8]);
                ah[mt][2] = __float_as_uint(Ah[(kb + tig + 4) * SAPAD + m0    ]);
                ah[mt][3] = __float_as_uint(Ah[(kb + tig + 4) * SAPAD + m0 + 8]);
                al[mt][0] = __float_as_uint(Al[(kb + tig    ) * SAPAD + m0    ]);
                al[mt][1] = __float_as_uint(Al[(kb + tig    ) * SAPAD + m0 + 8]);
                al[mt][2] = __float_as_uint(Al[(kb + tig + 4) * SAPAD + m0    ]);
                al[mt][3] = __float_as_uint(Al[(kb + tig + 4) * SAPAD + m0 + 8]);
            }
#pragma unroll
            for (int nt = 0; nt < 4; nt++) {
                int n0 = wn * 32 + nt * 8 + gID;
                uint32_t bh0 = __float_as_uint(Bh[(kb + tig    ) * SAPAD + n0]);
                uint32_t bh1 = __float_as_uint(Bh[(kb + tig + 4) * SAPAD + n0]);
                uint32_t bl0 = __float_as_uint(Bl[(kb + tig    ) * SAPAD + n0]);
                uint32_t bl1 = __float_as_uint(Bl[(kb + tig + 4) * SAPAD + n0]);
#pragma unroll
                for (int mt = 0; mt < 4; mt++) {
                    mma_tf32(acc[mt][nt], ah[mt][0], ah[mt][1], ah[mt][2], ah[mt][3], bh0, bh1);
                    mma_tf32(acc[mt][nt], al[mt][0], al[mt][1], al[mt][2], al[mt][3], bh0, bh1);
                    mma_tf32(acc[mt][nt], ah[mt][0], ah[mt][1], ah[mt][2], ah[mt][3], bl0, bl1);
                }
            }
        }
        __syncthreads();
    }

#pragma unroll
    for (int mt = 0; mt < 4; mt++) {
#pragma unroll
        for (int nt = 0; nt < 4; nt++) {
            int r0 = rowBase + wm * 64 + mt * 16 + gID;
            int c0 = colBase + wn * 32 + nt * 8 + tig * 2;
            float bi0 = bias ? bias[c0] : 0.f;
            float bi1 = bias ? bias[c0 + 1] : 0.f;
            float* p0 = C + (size_t)r0 * N + c0;
            float* p1 = C + (size_t)(r0 + 8) * N + c0;
            *(float2*)p0 = make_float2(acc[mt][nt][0] + bi0, acc[mt][nt][1] + bi1);
            *(float2*)p1 = make_float2(acc[mt][nt][2] + bi0, acc[mt][nt][3] + bi1);
        }
    }
}

// =====================================================================
// Persistent RNN recurrence v4 (proven R11): 512 threads, 16 warps,
// warp owns a 64-k slice; cg-style counter barrier.
// =====================================================================
__device__ __forceinline__ void red_add_release_gpu(int* p, int v)
{
    asm volatile("red.release.gpu.global.add.s32 [%0], %1;" :: "l"(p), "r"(v) : "memory");
}
__device__ __forceinline__ int ld_acquire_int(const int* p)
{
    int v;
    asm volatile("ld.acquire.gpu.global.s32 %0, [%1];" : "=r"(v) : "l"(p) : "memory");
    return v;
}

// transpose hidden[l] [B][H] -> g_h4 buf0 quad layout; reset barrier counter
__global__ __launch_bounds__(256)
void htrans_in_k(const float* __restrict__ hsrc)
{
    if (blockIdx.x == 0 && threadIdx.x == 0) g_ctr = 0;
    int idx = blockIdx.x * 256 + threadIdx.x;   // over 8192 quads
    int q = idx >> 5;          // 0..255  (k-quad)
    int b = idx & 31;
    float4 v = make_float4(hsrc[(size_t)b * HID + q * 4 + 0],
                           hsrc[(size_t)b * HID + q * 4 + 1],
                           hsrc[(size_t)b * HID + q * 4 + 2],
                           hsrc[(size_t)b * HID + q * 4 + 3]);
    g_h4[(size_t)q * BATCH + b] = v;
}

__global__ __launch_bounds__(512)
void rnn_persist(const float* __restrict__ xw,   // [128][32][1024]
                 const float* __restrict__ Whh,  // [1024][1024]
                 const float* __restrict__ bhh,  // [1024]
                 float* __restrict__ yseq)       // [128][32][1024]
{
    __shared__ float swT[HID][8];        // 32 KB: swT[k][j] = Whh[jbase+j][k]
    __shared__ float sb[8];
    __shared__ float red[16][BATCH][8];  // 16 KB partials

    int tid = threadIdx.x;
    int bid = blockIdx.x;
    int jbase = bid * 8;

    // load W slice transposed (coalesced gmem reads)
    for (int idx = tid; idx < 8 * HID; idx += 512) {
        int j = idx >> 10;
        int k = idx & 1023;
        swT[k][j] = Whh[(size_t)(jbase + j) * HID + k];
    }
    if (tid < 8) sb[tid] = bhh[jbase + tid];
    __syncthreads();

    int w    = tid >> 5;        // warp 0..15 -> 64-k slice
    int lane = tid & 31;        // lane -> batch
    int kqbase = w * 16;        // 16 quads (=64 k) per warp
    int rb = (tid >> 3) & 31;   // reduce: batch (threads 0..255)
    int rj = tid & 7;           // reduce: local j
    int jout = jbase + rj;
    int houtOff = ((jout >> 2) * BATCH + rb) * 4 + (jout & 3);

#pragma unroll 1
    for (int t = 0; t < T_LEN; t++) {
        const float4* hcur = g_h4 + (size_t)(t & 1) * (HID / 4) * BATCH;
        float*        hnxt = (float*)(g_h4 + (size_t)((t + 1) & 1) * (HID / 4) * BATCH);

        float xval = 0.f;
        if (tid < 256)
            xval = xw[(size_t)t * BATCH * HID + (size_t)rb * HID + jout];

        float acc[8];
#pragma unroll
        for (int j = 0; j < 8; j++) acc[j] = 0.f;

        float4 hv[8], hp[8];
#pragma unroll
        for (int i = 0; i < 8; i++)
            hv[i] = __ldcg(hcur + (size_t)(kqbase + i) * BATCH + lane);

#pragma unroll
        for (int c = 0; c < 2; c++) {
            if (c < 1) {
#pragma unroll
                for (int i = 0; i < 8; i++)
                    hp[i] = __ldcg(hcur + (size_t)(kqbase + 8 + i) * BATCH + lane);
            }
#pragma unroll
            for (int i = 0; i < 8; i++) {
                int k0 = (kqbase + c * 8 + i) * 4;
                float hd[4] = {hv[i].x, hv[i].y, hv[i].z, hv[i].w};
#pragma unroll
                for (int d = 0; d < 4; d++) {
                    float4 wa = *(const float4*)&swT[k0 + d][0];
                    float4 wb = *(const float4*)&swT[k0 + d][4];
                    acc[0] += wa.x * hd[d];
                    acc[1] += wa.y * hd[d];
                    acc[2] += wa.z * hd[d];
                    acc[3] += wa.w * hd[d];
                    acc[4] += wb.x * hd[d];
                    acc[5] += wb.y * hd[d];
                    acc[6] += wb.z * hd[d];
                    acc[7] += wb.w * hd[d];
                }
            }
            if (c < 1) {
#pragma unroll
                for (int i = 0; i < 8; i++) hv[i] = hp[i];
            }
        }

        // cross-warp (k-slice) reduction over 16 warps
        *(float4*)&red[w][lane][0] = make_float4(acc[0], acc[1], acc[2], acc[3]);
        *(float4*)&red[w][lane][4] = make_float4(acc[4], acc[5], acc[6], acc[7]);
        __syncthreads();
        if (tid < 256) {
            float s = 0.f;
#pragma unroll
            for (int ww = 0; ww < 16; ww++) s += red[ww][rb][rj];
            float v = tanhf(s + sb[rj] + xval);
            __stcg(hnxt + houtOff, v);
            yseq[(size_t)t * BATCH * HID + (size_t)rb * HID + jout] = v;
        }

        // grid barrier (single release-add + single acquire poller + sleep)
        __syncthreads();
        if (tid == 0) {
            red_add_release_gpu(&g_ctr, 1);
            int target = 128 * (t + 1);
            while (ld_acquire_int(&g_ctr) < target) {
                __nanosleep(64);
            }
        }
        __syncthreads();
    }
}

// =====================================================================
// In-place log_softmax over rows of 32000. Row cached in 128 KB smem.
// =====================================================================
__global__ __launch_bounds__(256)
void logsoftmax_k(float* __restrict__ out)
{
    extern __shared__ float srow[];
    __shared__ float red[256];
    int tid = threadIdx.x;
    float4* p4 = (float4*)(out + (size_t)blockIdx.x * VOCAB);

    float m = -3.4e38f;
#pragma unroll 4
    for (int i = tid; i < VOCAB / 4; i += 256) {
        float4 v = p4[i];
        *(float4*)&srow[i * 4] = v;
        m = fmaxf(m, fmaxf(fmaxf(v.x, v.y), fmaxf(v.z, v.w)));
    }
    red[tid] = m; __syncthreads();
    for (int s = 128; s > 0; s >>= 1) {
        if (tid < s) red[tid] = fmaxf(red[tid], red[tid + s]);
        __syncthreads();
    }
    float rm = red[0]; __syncthreads();

    float sum = 0.f;
    for (int i = tid; i < VOCAB; i += 256) sum += expf(srow[i] - rm);
    red[tid] = sum; __syncthreads();
    for (int s = 128; s > 0; s >>= 1) {
        if (tid < s) red[tid] += red[tid + s];
        __syncthreads();
    }
    float lz = rm + logf(red[0]);

    for (int i = tid; i < VOCAB / 4; i += 256) {
        float4 v = *(float4*)&srow[i * 4];
        v.x -= lz; v.y -= lz; v.z -= lz; v.w -= lz;
        p4[i] = v;
    }
}

// =====================================================================
// host orchestration (graph-capturable)
// =====================================================================
extern "C" void kernel_launch(void* const* d_in, const int* in_sizes, int n_in,
                              void* d_out, int out_size)
{
    const int*   input_x = (const int*)  d_in[0];
    const float* hidden  = (const float*)d_in[1];
    const float* emb     = (const float*)d_in[2];
    const float* W_ih    = (const float*)d_in[3];
    const float* W_hh    = (const float*)d_in[4];
    const float* b_ih    = (const float*)d_in[5];
    const float* b_hh    = (const float*)d_in[6];
    const float* W_out   = (const float*)d_in[7];
    const float* b_out   = (const float*)d_in[8];
    float* out = (float*)d_out;

    float *gx, *gxw;
    cudaGetSymbolAddress((void**)&gx,  g_x);
    cudaGetSymbolAddress((void**)&gxw, g_xw);

    cudaFuncSetAttribute(logsoftmax_k,
                         cudaFuncAttributeMaxDynamicSharedMemorySize,
                         VOCAB * (int)sizeof(float));
    cudaFuncSetAttribute(gemm_split3,
                         cudaFuncAttributeMaxDynamicSharedMemorySize,
                         4 * BK * SAPAD * (int)sizeof(float));
    cudaFuncSetAttribute(gemm_tf32,
                         cudaFuncAttributeMaxDynamicSharedMemorySize,
                         4 * OTILE * (int)sizeof(float));

    const int writeHidden = (size_t)out_size >= LOGITS_ELEMS + HIDDEN_ELEMS;

    // 1) embedding gather
    embed_k<<<MROWS, 256>>>(input_x, emb, gx);

    for (int l = 0; l < 2; l++) {
        const float* Wi = W_ih + (size_t)l * HID * HID;
        const float* Wh = W_hh + (size_t)l * HID * HID;
        const float* bi = b_ih + (size_t)l * HID;
        const float* bh = b_hh + (size_t)l * HID;

        // init transposed hidden (buf 0) + reset barrier counter
        htrans_in_k<<<BATCH * HID / 256, 256>>>(hidden + (size_t)l * BATCH * HID);

        // input projection: fused 3-term tf32 split, single launch
        dim3 gp(MROWS / BM, HID / BN);
        gemm_split3<<<gp, 256, 4 * BK * SAPAD * (int)sizeof(float)>>>(
            gx, Wi, gxw, bi, MROWS, HID, HID);

        // persistent recurrence (exact fp32), 512 threads
        rnn_persist<<<128, 512>>>(gxw, Wh, bh, gx);

        // new_hidden[l] = y[T-1]
        if (writeHidden)
            cudaMemcpyAsync(out + LOGITS_ELEMS + (size_t)l * BATCH * HID,
                            gx + (size_t)(T_LEN - 1) * BATCH * HID,
                            (size_t)BATCH * HID * sizeof(float),
                            cudaMemcpyDeviceToDevice, 0);
    }

    // output projection (R10 cp.async double-buffered HMMA tf32, 256 thr)
    dim3 go(MROWS / BM, VOCAB / BN);
    gemm_tf32<<<go, 256, 4 * OTILE * (int)sizeof(float)>>>(
        gx, W_out, out, b_out, MROWS, VOCAB, HID);

    // in-place log_softmax
    logsoftmax_k<<<MROWS, 256, VOCAB * (int)sizeof(float)>>>(out);
}

// round 13
// speedup vs baseline: 1.1119x; 1.0235x over previous
#include <cuda_runtime.h>
#include <cuda_bf16.h>
#include <cstdint>
#include <cstddef>

// ---------------- problem constants ----------------
#define T_LEN 128
#define BATCH 32
#define HID   1024
#define VOCAB 32000
#define MROWS (T_LEN * BATCH)        // 4096
#define LOGITS_ELEMS ((size_t)MROWS * VOCAB)   // 131072000
#define HIDDEN_ELEMS (2 * BATCH * HID)         // 65536

// ---------------- device scratch (no runtime alloc allowed) ----------------
__device__ float g_x [MROWS * HID];     // layer input / output sequence (16 MB)
__device__ float g_xw[MROWS * HID];     // precomputed input projection  (16 MB)
// hidden ping-pong, float4-quad layout: buf[q*BATCH + b] holds h[4q..4q+3][b]
__device__ float4 g_h4[2 * (HID / 4) * BATCH];
__device__ int   g_ctr;                 // persistent-kernel barrier counter

// =====================================================================
// Embedding gather
// =====================================================================
__global__ __launch_bounds__(256)
void embed_k(const int* __restrict__ idx, const float* __restrict__ emb,
             float* __restrict__ xout)
{
    int row = blockIdx.x;
    int tok = idx[row];
    const float4* s = (const float4*)(emb + (size_t)tok * HID);
    float4* d = (float4*)(xout + (size_t)row * HID);
    d[threadIdx.x] = s[threadIdx.x];
}

// =====================================================================
// tf32 helpers
// =====================================================================
__device__ __forceinline__ float tf32_hi(float v)
{
    uint32_t t;
    asm("cvt.rna.tf32.f32 %0, %1;" : "=r"(t) : "f"(v));
    return __uint_as_float(t);
}

__device__ __forceinline__ void mma_tf32(float c[4], uint32_t a0, uint32_t a1,
                                         uint32_t a2, uint32_t a3,
                                         uint32_t b0, uint32_t b1)
{
    asm volatile(
        "mma.sync.aligned.m16n8k8.row.col.f32.tf32.tf32.f32 "
        "{%0,%1,%2,%3}, {%4,%5,%6,%7}, {%8,%9}, {%0,%1,%2,%3};"
        : "+f"(c[0]), "+f"(c[1]), "+f"(c[2]), "+f"(c[3])
        : "r"(a0), "r"(a1), "r"(a2), "r"(a3), "r"(b0), "r"(b1));
}

__device__ __forceinline__ void cp16(uint32_t dst, const void* src)
{
    asm volatile("cp.async.cg.shared.global [%0], [%1], 16;" :: "r"(dst), "l"(src));
}

#define BM 128
#define BN 128
#define BK 32

// =====================================================================
// Output projection GEMM (R10 proven): C = A[M,K]*B[N,K]^T + bias.
// 256 threads, 8 warps 2x4, warp tile 64x32.
// cp.async double-buffered, raw f32 operands (HMMA.tf32 truncates in HW).
// Smem tiles [row][36] (conflict-free fragment LDS), 2 blocks/SM, 72 KB.
// =====================================================================
#define OSTR 36
#define OTILE (BM * OSTR)

__global__ __launch_bounds__(256, 2)
void gemm_tf32(const float* __restrict__ A, const float* __restrict__ B,
               float* __restrict__ C, const float* __restrict__ bias,
               int M, int N, int K)
{
    extern __shared__ float smem[];
    // layout: A0 | A1 | B0 | B1, each OTILE floats

    int tid  = threadIdx.x;
    int warp = tid >> 5, lane = tid & 31;
    int wm   = warp >> 2;
    int wn   = warp & 3;
    int gID  = lane >> 2;
    int tig  = lane & 3;

    int rowBase = blockIdx.x * BM;
    int colBase = blockIdx.y * BN;

    // stage mapping: 2 threads per tile row, each 64B (4 x 16B)
    int srow = tid >> 1;        // 0..127
    int shalf = tid & 1;        // 0..1 (16-float half of BK)
    const float* Asrc = A + (size_t)(rowBase + srow) * K + shalf * 16;
    const float* Bsrc = B + (size_t)(colBase + srow) * K + shalf * 16;
    uint32_t smemBase = (uint32_t)__cvta_generic_to_shared(smem);
    uint32_t aDst = smemBase + (uint32_t)(srow * OSTR + shalf * 16) * 4;
    uint32_t bDst = aDst + 2 * OTILE * 4;

    const int NT = K / BK;

    float acc[4][4][4];
#pragma unroll
    for (int mt = 0; mt < 4; mt++)
#pragma unroll
        for (int nt = 0; nt < 4; nt++)
#pragma unroll
            for (int q = 0; q < 4; q++) acc[mt][nt][q] = 0.f;

    // prologue: stage tile 0 into buffer 0
#pragma unroll
    for (int c = 0; c < 4; c++) {
        cp16(aDst + c * 16, Asrc + c * 4);
        cp16(bDst + c * 16, Bsrc + c * 4);
    }
    asm volatile("cp.async.commit_group;");

    for (int kt = 0; kt < NT; kt++) {
        int cur = kt & 1;
        if (kt + 1 < NT) {
            int nxt = cur ^ 1;
            const float* ap = Asrc + (size_t)(kt + 1) * BK;
            const float* bp = Bsrc + (size_t)(kt + 1) * BK;
            uint32_t ad = aDst + (uint32_t)nxt * OTILE * 4;
            uint32_t bd = bDst + (uint32_t)nxt * OTILE * 4;
#pragma unroll
            for (int c = 0; c < 4; c++) {
                cp16(ad + c * 16, ap + c * 4);
                cp16(bd + c * 16, bp + c * 4);
            }
            asm volatile("cp.async.commit_group;");
            asm volatile("cp.async.wait_group 1;");
        } else {
            asm volatile("cp.async.wait_group 0;");
        }
        __syncthreads();

        const float* sA = smem + cur * OTILE;
        const float* sB = smem + 2 * OTILE + cur * OTILE;

#pragma unroll
        for (int ks = 0; ks < 4; ks++) {
            int kb = ks * 8;
            uint32_t af[4][4];
#pragma unroll
            for (int mt = 0; mt < 4; mt++) {
                int m0 = wm * 64 + mt * 16 + gID;
                af[mt][0] = __float_as_uint(sA[(m0    ) * OSTR + kb + tig    ]);
                af[mt][1] = __float_as_uint(sA[(m0 + 8) * OSTR + kb + tig    ]);
                af[mt][2] = __float_as_uint(sA[(m0    ) * OSTR + kb + tig + 4]);
                af[mt][3] = __float_as_uint(sA[(m0 + 8) * OSTR + kb + tig + 4]);
            }
#pragma unroll
            for (int nt = 0; nt < 4; nt++) {
                int n0 = wn * 32 + nt * 8 + gID;
                uint32_t b0 = __float_as_uint(sB[n0 * OSTR + kb + tig    ]);
                uint32_t b1 = __float_as_uint(sB[n0 * OSTR + kb + tig + 4]);
#pragma unroll
                for (int mt = 0; mt < 4; mt++)
                    mma_tf32(acc[mt][nt], af[mt][0], af[mt][1], af[mt][2],
                             af[mt][3], b0, b1);
            }
        }
        __syncthreads();
    }

#pragma unroll
    for (int mt = 0; mt < 4; mt++) {
#pragma unroll
        for (int nt = 0; nt < 4; nt++) {
            int r0 = rowBase + wm * 64 + mt * 16 + gID;
            int c0 = colBase + wn * 32 + nt * 8 + tig * 2;
            float bi0 = bias ? bias[c0] : 0.f;
            float bi1 = bias ? bias[c0 + 1] : 0.f;
            float* p0 = C + (size_t)r0 * N + c0;
            float* p1 = C + (size_t)(r0 + 8) * N + c0;
            *(float2*)p0 = make_float2(acc[mt][nt][0] + bi0, acc[mt][nt][1] + bi1);
            *(float2*)p1 = make_float2(acc[mt][nt][2] + bi0, acc[mt][nt][3] + bi1);
        }
    }
}

// =====================================================================
// Input projection GEMM v2: 3-term tf32 split (near-fp32), cp.async
// double-buffered RAW tiles; hi/lo split done in FRAGMENT REGISTERS.
// Same rounding ops as old split3 -> bit-identical results, ~3x faster.
// acc += Ah*Bh + Al*Bh + Ah*Bl.
// =====================================================================
__global__ __launch_bounds__(256, 2)
void gemm_split3(const float* __restrict__ A, const float* __restrict__ B,
                 float* __restrict__ C, const float* __restrict__ bias,
                 int M, int N, int K)
{
    extern __shared__ float smem[];
    // layout: A0 | A1 | B0 | B1, each OTILE floats

    int tid  = threadIdx.x;
    int warp = tid >> 5, lane = tid & 31;
    int wm   = warp >> 2;
    int wn   = warp & 3;
    int gID  = lane >> 2;
    int tig  = lane & 3;

    int rowBase = blockIdx.x * BM;
    int colBase = blockIdx.y * BN;

    int srow = tid >> 1;
    int shalf = tid & 1;
    const float* Asrc = A + (size_t)(rowBase + srow) * K + shalf * 16;
    const float* Bsrc = B + (size_t)(colBase + srow) * K + shalf * 16;
    uint32_t smemBase = (uint32_t)__cvta_generic_to_shared(smem);
    uint32_t aDst = smemBase + (uint32_t)(srow * OSTR + shalf * 16) * 4;
    uint32_t bDst = aDst + 2 * OTILE * 4;

    const int NT = K / BK;

    float acc[4][4][4];
#pragma unroll
    for (int mt = 0; mt < 4; mt++)
#pragma unroll
        for (int nt = 0; nt < 4; nt++)
#pragma unroll
            for (int q = 0; q < 4; q++) acc[mt][nt][q] = 0.f;

    // prologue
#pragma unroll
    for (int c = 0; c < 4; c++) {
        cp16(aDst + c * 16, Asrc + c * 4);
        cp16(bDst + c * 16, Bsrc + c * 4);
    }
    asm volatile("cp.async.commit_group;");

    for (int kt = 0; kt < NT; kt++) {
        int cur = kt & 1;
        if (kt + 1 < NT) {
            int nxt = cur ^ 1;
            const float* ap = Asrc + (size_t)(kt + 1) * BK;
            const float* bp = Bsrc + (size_t)(kt + 1) * BK;
            uint32_t ad = aDst + (uint32_t)nxt * OTILE * 4;
            uint32_t bd = bDst + (uint32_t)nxt * OTILE * 4;
#pragma unroll
            for (int c = 0; c < 4; c++) {
                cp16(ad + c * 16, ap + c * 4);
                cp16(bd + c * 16, bp + c * 4);
            }
            asm volatile("cp.async.commit_group;");
            asm volatile("cp.async.wait_group 1;");
        } else {
            asm volatile("cp.async.wait_group 0;");
        }
        __syncthreads();

        const float* sA = smem + cur * OTILE;
        const float* sB = smem + 2 * OTILE + cur * OTILE;

#pragma unroll
        for (int ks = 0; ks < 4; ks++) {
            int kb = ks * 8;
            uint32_t ah[4][4], al[4][4];
#pragma unroll
            for (int mt = 0; mt < 4; mt++) {
                int m0 = wm * 64 + mt * 16 + gID;
                float r0 = sA[(m0    ) * OSTR + kb + tig    ];
                float r1 = sA[(m0 + 8) * OSTR + kb + tig    ];
                float r2 = sA[(m0    ) * OSTR + kb + tig + 4];
                float r3 = sA[(m0 + 8) * OSTR + kb + tig + 4];
                float h;
                h = tf32_hi(r0); ah[mt][0] = __float_as_uint(h);
                al[mt][0] = __float_as_uint(tf32_hi(r0 - h));
                h = tf32_hi(r1); ah[mt][1] = __float_as_uint(h);
                al[mt][1] = __float_as_uint(tf32_hi(r1 - h));
                h = tf32_hi(r2); ah[mt][2] = __float_as_uint(h);
                al[mt][2] = __float_as_uint(tf32_hi(r2 - h));
                h = tf32_hi(r3); ah[mt][3] = __float_as_uint(h);
                al[mt][3] = __float_as_uint(tf32_hi(r3 - h));
            }
#pragma unroll
            for (int nt = 0; nt < 4; nt++) {
                int n0 = wn * 32 + nt * 8 + gID;
                float br0 = sB[n0 * OSTR + kb + tig    ];
                float br1 = sB[n0 * OSTR + kb + tig + 4];
                float h0 = tf32_hi(br0);
                float h1 = tf32_hi(br1);
                uint32_t bh0 = __float_as_uint(h0);
                uint32_t bh1 = __float_as_uint(h1);
                uint32_t bl0 = __float_as_uint(tf32_hi(br0 - h0));
                uint32_t bl1 = __float_as_uint(tf32_hi(br1 - h1));
#pragma unroll
                for (int mt = 0; mt < 4; mt++) {
                    mma_tf32(acc[mt][nt], ah[mt][0], ah[mt][1], ah[mt][2], ah[mt][3], bh0, bh1);
                    mma_tf32(acc[mt][nt], al[mt][0], al[mt][1], al[mt][2], al[mt][3], bh0, bh1);
                    mma_tf32(acc[mt][nt], ah[mt][0], ah[mt][1], ah[mt][2], ah[mt][3], bl0, bl1);
                }
            }
        }
        __syncthreads();
    }

#pragma unroll
    for (int mt = 0; mt < 4; mt++) {
#pragma unroll
        for (int nt = 0; nt < 4; nt++) {
            int r0 = rowBase + wm * 64 + mt * 16 + gID;
            int c0 = colBase + wn * 32 + nt * 8 + tig * 2;
            float bi0 = bias ? bias[c0] : 0.f;
            float bi1 = bias ? bias[c0 + 1] : 0.f;
            float* p0 = C + (size_t)r0 * N + c0;
            float* p1 = C + (size_t)(r0 + 8) * N + c0;
            *(float2*)p0 = make_float2(acc[mt][nt][0] + bi0, acc[mt][nt][1] + bi1);
            *(float2*)p1 = make_float2(acc[mt][nt][2] + bi0, acc[mt][nt][3] + bi1);
        }
    }
}

// =====================================================================
// Persistent RNN recurrence v4 (proven R11): 512 threads, 16 warps,
// warp owns a 64-k slice; cg-style counter barrier.
// =====================================================================
__device__ __forceinline__ void red_add_release_gpu(int* p, int v)
{
    asm volatile("red.release.gpu.global.add.s32 [%0], %1;" :: "l"(p), "r"(v) : "memory");
}
__device__ __forceinline__ int ld_acquire_int(const int* p)
{
    int v;
    asm volatile("ld.acquire.gpu.global.s32 %0, [%1];" : "=r"(v) : "l"(p) : "memory");
    return v;
}

// transpose hidden[l] [B][H] -> g_h4 buf0 quad layout; reset barrier counter
__global__ __launch_bounds__(256)
void htrans_in_k(const float* __restrict__ hsrc)
{
    if (blockIdx.x == 0 && threadIdx.x == 0) g_ctr = 0;
    int idx = blockIdx.x * 256 + threadIdx.x;   // over 8192 quads
    int q = idx >> 5;          // 0..255  (k-quad)
    int b = idx & 31;
    float4 v = make_float4(hsrc[(size_t)b * HID + q * 4 + 0],
                           hsrc[(size_t)b * HID + q * 4 + 1],
                           hsrc[(size_t)b * HID + q * 4 + 2],
                           hsrc[(size_t)b * HID + q * 4 + 3]);
    g_h4[(size_t)q * BATCH + b] = v;
}

__global__ __launch_bounds__(512)
void rnn_persist(const float* __restrict__ xw,   // [128][32][1024]
                 const float* __restrict__ Whh,  // [1024][1024]
                 const float* __restrict__ bhh,  // [1024]
                 float* __restrict__ yseq)       // [128][32][1024]
{
    __shared__ float swT[HID][8];        // 32 KB: swT[k][j] = Whh[jbase+j][k]
    __shared__ float sb[8];
    __shared__ float red[16][BATCH][8];  // 16 KB partials

    int tid = threadIdx.x;
    int bid = blockIdx.x;
    int jbase = bid * 8;

    // load W slice transposed (coalesced gmem reads)
    for (int idx = tid; idx < 8 * HID; idx += 512) {
        int j = idx >> 10;
        int k = idx & 1023;
        swT[k][j] = Whh[(size_t)(jbase + j) * HID + k];
    }
    if (tid < 8) sb[tid] = bhh[jbase + tid];
    __syncthreads();

    int w    = tid >> 5;        // warp 0..15 -> 64-k slice
    int lane = tid & 31;        // lane -> batch
    int kqbase = w * 16;        // 16 quads (=64 k) per warp
    int rb = (tid >> 3) & 31;   // reduce: batch (threads 0..255)
    int rj = tid & 7;           // reduce: local j
    int jout = jbase + rj;
    int houtOff = ((jout >> 2) * BATCH + rb) * 4 + (jout & 3);

#pragma unroll 1
    for (int t = 0; t < T_LEN; t++) {
        const float4* hcur = g_h4 + (size_t)(t & 1) * (HID / 4) * BATCH;
        float*        hnxt = (float*)(g_h4 + (size_t)((t + 1) & 1) * (HID / 4) * BATCH);

        float xval = 0.f;
        if (tid < 256)
            xval = xw[(size_t)t * BATCH * HID + (size_t)rb * HID + jout];

        float acc[8];
#pragma unroll
        for (int j = 0; j < 8; j++) acc[j] = 0.f;

        float4 hv[8], hp[8];
#pragma unroll
        for (int i = 0; i < 8; i++)
            hv[i] = __ldcg(hcur + (size_t)(kqbase + i) * BATCH + lane);

#pragma unroll
        for (int c = 0; c < 2; c++) {
            if (c < 1) {
#pragma unroll
                for (int i = 0; i < 8; i++)
                    hp[i] = __ldcg(hcur + (size_t)(kqbase + 8 + i) * BATCH + lane);
            }
#pragma unroll
            for (int i = 0; i < 8; i++) {
                int k0 = (kqbase + c * 8 + i) * 4;
                float hd[4] = {hv[i].x, hv[i].y, hv[i].z, hv[i].w};
#pragma unroll
                for (int d = 0; d < 4; d++) {
                    float4 wa = *(const float4*)&swT[k0 + d][0];
                    float4 wb = *(const float4*)&swT[k0 + d][4];
                    acc[0] += wa.x * hd[d];
                    acc[1] += wa.y * hd[d];
                    acc[2] += wa.z * hd[d];
                    acc[3] += wa.w * hd[d];
                    acc[4] += wb.x * hd[d];
                    acc[5] += wb.y * hd[d];
                    acc[6] += wb.z * hd[d];
                    acc[7] += wb.w * hd[d];
                }
            }
            if (c < 1) {
#pragma unroll
                for (int i = 0; i < 8; i++) hv[i] = hp[i];
            }
        }

        // cross-warp (k-slice) reduction over 16 warps
        *(float4*)&red[w][lane][0] = make_float4(acc[0], acc[1], acc[2], acc[3]);
        *(float4*)&red[w][lane][4] = make_float4(acc[4], acc[5], acc[6], acc[7]);
        __syncthreads();
        if (tid < 256) {
            float s = 0.f;
#pragma unroll
            for (int ww = 0; ww < 16; ww++) s += red[ww][rb][rj];
            float v = tanhf(s + sb[rj] + xval);
            __stcg(hnxt + houtOff, v);
            yseq[(size_t)t * BATCH * HID + (size_t)rb * HID + jout] = v;
        }

        // grid barrier (single release-add + single acquire poller + sleep)
        __syncthreads();
        if (tid == 0) {
            red_add_release_gpu(&g_ctr, 1);
            int target = 128 * (t + 1);
            while (ld_acquire_int(&g_ctr) < target) {
                __nanosleep(64);
            }
        }
        __syncthreads();
    }
}

// =====================================================================
// In-place log_softmax over rows of 32000. Row cached in 128 KB smem.
// =====================================================================
__global__ __launch_bounds__(256)
void logsoftmax_k(float* __restrict__ out)
{
    extern __shared__ float srow[];
    __shared__ float red[256];
    int tid = threadIdx.x;
    float4* p4 = (float4*)(out + (size_t)blockIdx.x * VOCAB);

    float m = -3.4e38f;
#pragma unroll 4
    for (int i = tid; i < VOCAB / 4; i += 256) {
        float4 v = p4[i];
        *(float4*)&srow[i * 4] = v;
        m = fmaxf(m, fmaxf(fmaxf(v.x, v.y), fmaxf(v.z, v.w)));
    }
    red[tid] = m; __syncthreads();
    for (int s = 128; s > 0; s >>= 1) {
        if (tid < s) red[tid] = fmaxf(red[tid], red[tid + s]);
        __syncthreads();
    }
    float rm = red[0]; __syncthreads();

    float sum = 0.f;
    for (int i = tid; i < VOCAB; i += 256) sum += expf(srow[i] - rm);
    red[tid] = sum; __syncthreads();
    for (int s = 128; s > 0; s >>= 1) {
        if (tid < s) red[tid] += red[tid + s];
        __syncthreads();
    }
    float lz = rm + logf(red[0]);

    for (int i = tid; i < VOCAB / 4; i += 256) {
        float4 v = *(float4*)&srow[i * 4];
        v.x -= lz; v.y -= lz; v.z -= lz; v.w -= lz;
        p4[i] = v;
    }
}

// =====================================================================
// host orchestration (graph-capturable)
// =====================================================================
extern "C" void kernel_launch(void* const* d_in, const int* in_sizes, int n_in,
                              void* d_out, int out_size)
{
    const int*   input_x = (const int*)  d_in[0];
    const float* hidden  = (const float*)d_in[1];
    const float* emb     = (const float*)d_in[2];
    const float* W_ih    = (const float*)d_in[3];
    const float* W_hh    = (const float*)d_in[4];
    const float* b_ih    = (const float*)d_in[5];
    const float* b_hh    = (const float*)d_in[6];
    const float* W_out   = (const float*)d_in[7];
    const float* b_out   = (const float*)d_in[8];
    float* out = (float*)d_out;

    float *gx, *gxw;
    cudaGetSymbolAddress((void**)&gx,  g_x);
    cudaGetSymbolAddress((void**)&gxw, g_xw);

    cudaFuncSetAttribute(logsoftmax_k,
                         cudaFuncAttributeMaxDynamicSharedMemorySize,
                         VOCAB * (int)sizeof(float));
    cudaFuncSetAttribute(gemm_split3,
                         cudaFuncAttributeMaxDynamicSharedMemorySize,
                         4 * OTILE * (int)sizeof(float));
    cudaFuncSetAttribute(gemm_tf32,
                         cudaFuncAttributeMaxDynamicSharedMemorySize,
                         4 * OTILE * (int)sizeof(float));

    const int writeHidden = (size_t)out_size >= LOGITS_ELEMS + HIDDEN_ELEMS;

    // 1) embedding gather
    embed_k<<<MROWS, 256>>>(input_x, emb, gx);

    for (int l = 0; l < 2; l++) {
        const float* Wi = W_ih + (size_t)l * HID * HID;
        const float* Wh = W_hh + (size_t)l * HID * HID;
        const float* bi = b_ih + (size_t)l * HID;
        const float* bh = b_hh + (size_t)l * HID;

        // init transposed hidden (buf 0) + reset barrier counter
        htrans_in_k<<<BATCH * HID / 256, 256>>>(hidden + (size_t)l * BATCH * HID);

        // input projection: cp.async 3-term tf32 split, single launch
        dim3 gp(MROWS / BM, HID / BN);
        gemm_split3<<<gp, 256, 4 * OTILE * (int)sizeof(float)>>>(
            gx, Wi, gxw, bi, MROWS, HID, HID);

        // persistent recurrence (exact fp32), 512 threads
        rnn_persist<<<128, 512>>>(gxw, Wh, bh, gx);

        // new_hidden[l] = y[T-1]
        if (writeHidden)
            cudaMemcpyAsync(out + LOGITS_ELEMS + (size_t)l * BATCH * HID,
                            gx + (size_t)(T_LEN - 1) * BATCH * HID,
                            (size_t)BATCH * HID * sizeof(float),
                            cudaMemcpyDeviceToDevice, 0);
    }

    // output projection (R10 cp.async double-buffered HMMA tf32, 256 thr)
    dim3 go(MROWS / BM, VOCAB / BN);
    gemm_tf32<<<go, 256, 4 * OTILE * (int)sizeof(float)>>>(
        gx, W_out, out, b_out, MROWS, VOCAB, HID);

    // in-place log_softmax
    logsoftmax_k<<<MROWS, 256, VOCAB * (int)sizeof(float)>>>(out);
}

// round 16
// speedup vs baseline: 1.1187x; 1.0061x over previous
#include <cuda_runtime.h>
#include <cuda_bf16.h>
#include <cstdint>
#include <cstddef>

// ---------------- problem constants ----------------
#define T_LEN 128
#define BATCH 32
#define HID   1024
#define VOCAB 32000
#define MROWS (T_LEN * BATCH)        // 4096
#define LOGITS_ELEMS ((size_t)MROWS * VOCAB)   // 131072000
#define HIDDEN_ELEMS (2 * BATCH * HID)         // 65536

// ---------------- device scratch (no runtime alloc allowed) ----------------
__device__ float g_x [MROWS * HID];     // layer input / output sequence (16 MB)
__device__ float g_xw[MROWS * HID];     // precomputed input projection  (16 MB)
// hidden ping-pong, float4-quad layout: buf[q*BATCH + b] holds h[4q..4q+3][b]
__device__ float4 g_h4[2 * (HID / 4) * BATCH];
__device__ int   g_ctr;                 // persistent-kernel barrier counter

// =====================================================================
// Embedding gather
// =====================================================================
__global__ __launch_bounds__(256)
void embed_k(const int* __restrict__ idx, const float* __restrict__ emb,
             float* __restrict__ xout)
{
    int row = blockIdx.x;
    int tok = idx[row];
    const float4* s = (const float4*)(emb + (size_t)tok * HID);
    float4* d = (float4*)(xout + (size_t)row * HID);
    d[threadIdx.x] = s[threadIdx.x];
}

// =====================================================================
// tf32 / mma helpers
// =====================================================================
__device__ __forceinline__ float tf32_hi(float v)
{
    uint32_t t;
    asm("cvt.rna.tf32.f32 %0, %1;" : "=r"(t) : "f"(v));
    return __uint_as_float(t);
}

__device__ __forceinline__ void mma_tf32(float c[4], uint32_t a0, uint32_t a1,
                                         uint32_t a2, uint32_t a3,
                                         uint32_t b0, uint32_t b1)
{
    asm volatile(
        "mma.sync.aligned.m16n8k8.row.col.f32.tf32.tf32.f32 "
        "{%0,%1,%2,%3}, {%4,%5,%6,%7}, {%8,%9}, {%0,%1,%2,%3};"
        : "+f"(c[0]), "+f"(c[1]), "+f"(c[2]), "+f"(c[3])
        : "r"(a0), "r"(a1), "r"(a2), "r"(a3), "r"(b0), "r"(b1));
}

__device__ __forceinline__ void cp16(uint32_t dst, const void* src)
{
    asm volatile("cp.async.cg.shared.global [%0], [%1], 16;" :: "r"(dst), "l"(src));
}

#define BM 128
#define BN 128
#define BK 32
#define OSTR 36
#define OTILE (BM * OSTR)

// =====================================================================
// Output projection GEMM v4: C = A[M,K]*B[N,K]^T + bias.
// 256 threads, 8 warps 2x4, warp tile 64x32. Raw f32 operands
// (HMMA.tf32 truncates in HW). 3-STAGE cp.async pipeline with a single
// __syncthreads per K-iteration:
//   wait_group(1) -> sync -> issue tile kt+2 -> compute tile kt
// The issue targets slot (kt-1)%3, finished by all threads before this
// iteration's sync (program order), so one barrier suffices.
// Smem: 6 tiles x 18KB = 110.6 KB; 2 blocks/SM = 221 KB <= 228 KB.
// =====================================================================
__global__ __launch_bounds__(256, 2)
void gemm_tf32(const float* __restrict__ A, const float* __restrict__ B,
               float* __restrict__ C, const float* __restrict__ bias,
               int M, int N, int K)
{
    extern __shared__ float smem[];
    // layout: A0 | A1 | A2 | B0 | B1 | B2, each OTILE floats

    int tid  = threadIdx.x;
    int warp = tid >> 5, lane = tid & 31;
    int wm   = warp >> 2;
    int wn   = warp & 3;
    int gID  = lane >> 2;
    int tig  = lane & 3;

    int rowBase = blockIdx.x * BM;
    int colBase = blockIdx.y * BN;

    // stage mapping: 2 threads per tile row, each 64B (4 x 16B)
    int srow = tid >> 1;        // 0..127
    int shalf = tid & 1;        // 0..1 (16-float half of BK)
    const float* Asrc = A + (size_t)(rowBase + srow) * K + shalf * 16;
    const float* Bsrc = B + (size_t)(colBase + srow) * K + shalf * 16;
    uint32_t smemBase = (uint32_t)__cvta_generic_to_shared(smem);
    uint32_t aDst = smemBase + (uint32_t)(srow * OSTR + shalf * 16) * 4;
    uint32_t bDst = aDst + 3 * OTILE * 4;

    const int NT = K / BK;      // 32

    float acc[4][4][4];
#pragma unroll
    for (int mt = 0; mt < 4; mt++)
#pragma unroll
        for (int nt = 0; nt < 4; nt++)
#pragma unroll
            for (int q = 0; q < 4; q++) acc[mt][nt][q] = 0.f;

    // prologue: stage tiles 0 and 1 into slots 0 and 1
#pragma unroll
    for (int s = 0; s < 2; s++) {
        const float* ap = Asrc + (size_t)s * BK;
        const float* bp = Bsrc + (size_t)s * BK;
        uint32_t ad = aDst + (uint32_t)s * OTILE * 4;
        uint32_t bd = bDst + (uint32_t)s * OTILE * 4;
#pragma unroll
        for (int c = 0; c < 4; c++) {
            cp16(ad + c * 16, ap + c * 4);
            cp16(bd + c * 16, bp + c * 4);
        }
        asm volatile("cp.async.commit_group;");
    }

    int slot = 0;               // kt % 3
    int nslot = 2;              // (kt+2) % 3
    for (int kt = 0; kt < NT; kt++) {
        if (kt == NT - 1) {
            asm volatile("cp.async.wait_group 0;");
        } else {
            asm volatile("cp.async.wait_group 1;");
        }
        __syncthreads();

        if (kt + 2 < NT) {
            const float* ap = Asrc + (size_t)(kt + 2) * BK;
            const float* bp = Bsrc + (size_t)(kt + 2) * BK;
            uint32_t ad = aDst + (uint32_t)nslot * OTILE * 4;
            uint32_t bd = bDst + (uint32_t)nslot * OTILE * 4;
#pragma unroll
            for (int c = 0; c < 4; c++) {
                cp16(ad + c * 16, ap + c * 4);
                cp16(bd + c * 16, bp + c * 4);
            }
            asm volatile("cp.async.commit_group;");
        }

        const float* sA = smem + slot * OTILE;
        const float* sB = smem + 3 * OTILE + slot * OTILE;

#pragma unroll
        for (int ks = 0; ks < 4; ks++) {
            int kb = ks * 8;
            uint32_t af[4][4];
#pragma unroll
            for (int mt = 0; mt < 4; mt++) {
                int m0 = wm * 64 + mt * 16 + gID;
                af[mt][0] = __float_as_uint(sA[(m0    ) * OSTR + kb + tig    ]);
                af[mt][1] = __float_as_uint(sA[(m0 + 8) * OSTR + kb + tig    ]);
                af[mt][2] = __float_as_uint(sA[(m0    ) * OSTR + kb + tig + 4]);
                af[mt][3] = __float_as_uint(sA[(m0 + 8) * OSTR + kb + tig + 4]);
            }
#pragma unroll
            for (int nt = 0; nt < 4; nt++) {
                int n0 = wn * 32 + nt * 8 + gID;
                uint32_t b0 = __float_as_uint(sB[n0 * OSTR + kb + tig    ]);
                uint32_t b1 = __float_as_uint(sB[n0 * OSTR + kb + tig + 4]);
#pragma unroll
                for (int mt = 0; mt < 4; mt++)
                    mma_tf32(acc[mt][nt], af[mt][0], af[mt][1], af[mt][2],
                             af[mt][3], b0, b1);
            }
        }

        slot = (slot == 2) ? 0 : slot + 1;
        nslot = (nslot == 2) ? 0 : nslot + 1;
    }

#pragma unroll
    for (int mt = 0; mt < 4; mt++) {
#pragma unroll
        for (int nt = 0; nt < 4; nt++) {
            int r0 = rowBase + wm * 64 + mt * 16 + gID;
            int c0 = colBase + wn * 32 + nt * 8 + tig * 2;
            float bi0 = bias ? bias[c0] : 0.f;
            float bi1 = bias ? bias[c0 + 1] : 0.f;
            float* p0 = C + (size_t)r0 * N + c0;
            float* p1 = C + (size_t)(r0 + 8) * N + c0;
            *(float2*)p0 = make_float2(acc[mt][nt][0] + bi0, acc[mt][nt][1] + bi1);
            *(float2*)p1 = make_float2(acc[mt][nt][2] + bi0, acc[mt][nt][3] + bi1);
        }
    }
}

// =====================================================================
// Input projection GEMM (R13 proven): 3-term tf32 split, cp.async
// double-buffered raw tiles; hi/lo split in fragment registers.
// =====================================================================
__global__ __launch_bounds__(256, 2)
void gemm_split3(const float* __restrict__ A, const float* __restrict__ B,
                 float* __restrict__ C, const float* __restrict__ bias,
                 int M, int N, int K)
{
    extern __shared__ float smem[];

    int tid  = threadIdx.x;
    int warp = tid >> 5, lane = tid & 31;
    int wm   = warp >> 2;
    int wn   = warp & 3;
    int gID  = lane >> 2;
    int tig  = lane & 3;

    int rowBase = blockIdx.x * BM;
    int colBase = blockIdx.y * BN;

    int srow = tid >> 1;
    int shalf = tid & 1;
    const float* Asrc = A + (size_t)(rowBase + srow) * K + shalf * 16;
    const float* Bsrc = B + (size_t)(colBase + srow) * K + shalf * 16;
    uint32_t smemBase = (uint32_t)__cvta_generic_to_shared(smem);
    uint32_t aDst = smemBase + (uint32_t)(srow * OSTR + shalf * 16) * 4;
    uint32_t bDst = aDst + 2 * OTILE * 4;

    const int NT = K / BK;

    float acc[4][4][4];
#pragma unroll
    for (int mt = 0; mt < 4; mt++)
#pragma unroll
        for (int nt = 0; nt < 4; nt++)
#pragma unroll
            for (int q = 0; q < 4; q++) acc[mt][nt][q] = 0.f;

#pragma unroll
    for (int c = 0; c < 4; c++) {
        cp16(aDst + c * 16, Asrc + c * 4);
        cp16(bDst + c * 16, Bsrc + c * 4);
    }
    asm volatile("cp.async.commit_group;");

    for (int kt = 0; kt < NT; kt++) {
        int cur = kt & 1;
        if (kt + 1 < NT) {
            int nxt = cur ^ 1;
            const float* ap = Asrc + (size_t)(kt + 1) * BK;
            const float* bp = Bsrc + (size_t)(kt + 1) * BK;
            uint32_t ad = aDst + (uint32_t)nxt * OTILE * 4;
            uint32_t bd = bDst + (uint32_t)nxt * OTILE * 4;
#pragma unroll
            for (int c = 0; c < 4; c++) {
                cp16(ad + c * 16, ap + c * 4);
                cp16(bd + c * 16, bp + c * 4);
            }
            asm volatile("cp.async.commit_group;");
            asm volatile("cp.async.wait_group 1;");
        } else {
            asm volatile("cp.async.wait_group 0;");
        }
        __syncthreads();

        const float* sA = smem + cur * OTILE;
        const float* sB = smem + 2 * OTILE + cur * OTILE;

#pragma unroll
        for (int ks = 0; ks < 4; ks++) {
            int kb = ks * 8;
            uint32_t ah[4][4], al[4][4];
#pragma unroll
            for (int mt = 0; mt < 4; mt++) {
                int m0 = wm * 64 + mt * 16 + gID;
                float r0 = sA[(m0    ) * OSTR + kb + tig    ];
                float r1 = sA[(m0 + 8) * OSTR + kb + tig    ];
                float r2 = sA[(m0    ) * OSTR + kb + tig + 4];
                float r3 = sA[(m0 + 8) * OSTR + kb + tig + 4];
                float h;
                h = tf32_hi(r0); ah[mt][0] = __float_as_uint(h);
                al[mt][0] = __float_as_uint(tf32_hi(r0 - h));
                h = tf32_hi(r1); ah[mt][1] = __float_as_uint(h);
                al[mt][1] = __float_as_uint(tf32_hi(r1 - h));
                h = tf32_hi(r2); ah[mt][2] = __float_as_uint(h);
                al[mt][2] = __float_as_uint(tf32_hi(r2 - h));
                h = tf32_hi(r3); ah[mt][3] = __float_as_uint(h);
                al[mt][3] = __float_as_uint(tf32_hi(r3 - h));
            }
#pragma unroll
            for (int nt = 0; nt < 4; nt++) {
                int n0 = wn * 32 + nt * 8 + gID;
                float br0 = sB[n0 * OSTR + kb + tig    ];
                float br1 = sB[n0 * OSTR + kb + tig + 4];
                float h0 = tf32_hi(br0);
                float h1 = tf32_hi(br1);
                uint32_t bh0 = __float_as_uint(h0);
                uint32_t bh1 = __float_as_uint(h1);
                uint32_t bl0 = __float_as_uint(tf32_hi(br0 - h0));
                uint32_t bl1 = __float_as_uint(tf32_hi(br1 - h1));
#pragma unroll
                for (int mt = 0; mt < 4; mt++) {
                    mma_tf32(acc[mt][nt], ah[mt][0], ah[mt][1], ah[mt][2], ah[mt][3], bh0, bh1);
                    mma_tf32(acc[mt][nt], al[mt][0], al[mt][1], al[mt][2], al[mt][3], bh0, bh1);
                    mma_tf32(acc[mt][nt], ah[mt][0], ah[mt][1], ah[mt][2], ah[mt][3], bl0, bl1);
                }
            }
        }
        __syncthreads();
    }

#pragma unroll
    for (int mt = 0; mt < 4; mt++) {
#pragma unroll
        for (int nt = 0; nt < 4; nt++) {
            int r0 = rowBase + wm * 64 + mt * 16 + gID;
            int c0 = colBase + wn * 32 + nt * 8 + tig * 2;
            float bi0 = bias ? bias[c0] : 0.f;
            float bi1 = bias ? bias[c0 + 1] : 0.f;
            float* p0 = C + (size_t)r0 * N + c0;
            float* p1 = C + (size_t)(r0 + 8) * N + c0;
            *(float2*)p0 = make_float2(acc[mt][nt][0] + bi0, acc[mt][nt][1] + bi1);
            *(float2*)p1 = make_float2(acc[mt][nt][2] + bi0, acc[mt][nt][3] + bi1);
        }
    }
}

// =====================================================================
// Persistent RNN recurrence v4 (proven R11): 512 threads, 16 warps,
// warp owns a 64-k slice; cg-style counter barrier.
// =====================================================================
__device__ __forceinline__ void red_add_release_gpu(int* p, int v)
{
    asm volatile("red.release.gpu.global.add.s32 [%0], %1;" :: "l"(p), "r"(v) : "memory");
}
__device__ __forceinline__ int ld_acquire_int(const int* p)
{
    int v;
    asm volatile("ld.acquire.gpu.global.s32 %0, [%1];" : "=r"(v) : "l"(p) : "memory");
    return v;
}

// transpose hidden[l] [B][H] -> g_h4 buf0 quad layout; reset barrier counter
__global__ __launch_bounds__(256)
void htrans_in_k(const float* __restrict__ hsrc)
{
    if (blockIdx.x == 0 && threadIdx.x == 0) g_ctr = 0;
    int idx = blockIdx.x * 256 + threadIdx.x;   // over 8192 quads
    int q = idx >> 5;          // 0..255  (k-quad)
    int b = idx & 31;
    float4 v = make_float4(hsrc[(size_t)b * HID + q * 4 + 0],
                           hsrc[(size_t)b * HID + q * 4 + 1],
                           hsrc[(size_t)b * HID + q * 4 + 2],
                           hsrc[(size_t)b * HID + q * 4 + 3]);
    g_h4[(size_t)q * BATCH + b] = v;
}

__global__ __launch_bounds__(512)
void rnn_persist(const float* __restrict__ xw,   // [128][32][1024]
                 const float* __restrict__ Whh,  // [1024][1024]
                 const float* __restrict__ bhh,  // [1024]
                 float* __restrict__ yseq)       // [128][32][1024]
{
    __shared__ float swT[HID][8];        // 32 KB: swT[k][j] = Whh[jbase+j][k]
    __shared__ float sb[8];
    __shared__ float red[16][BATCH][8];  // 16 KB partials

    int tid = threadIdx.x;
    int bid = blockIdx.x;
    int jbase = bid * 8;

    for (int idx = tid; idx < 8 * HID; idx += 512) {
        int j = idx >> 10;
        int k = idx & 1023;
        swT[k][j] = Whh[(size_t)(jbase + j) * HID + k];
    }
    if (tid < 8) sb[tid] = bhh[jbase + tid];
    __syncthreads();

    int w    = tid >> 5;        // warp 0..15 -> 64-k slice
    int lane = tid & 31;        // lane -> batch
    int kqbase = w * 16;        // 16 quads (=64 k) per warp
    int rb = (tid >> 3) & 31;   // reduce: batch (threads 0..255)
    int rj = tid & 7;           // reduce: local j
    int jout = jbase + rj;
    int houtOff = ((jout >> 2) * BATCH + rb) * 4 + (jout & 3);

#pragma unroll 1
    for (int t = 0; t < T_LEN; t++) {
        const float4* hcur = g_h4 + (size_t)(t & 1) * (HID / 4) * BATCH;
        float*        hnxt = (float*)(g_h4 + (size_t)((t + 1) & 1) * (HID / 4) * BATCH);

        float xval = 0.f;
        if (tid < 256)
            xval = xw[(size_t)t * BATCH * HID + (size_t)rb * HID + jout];

        float acc[8];
#pragma unroll
        for (int j = 0; j < 8; j++) acc[j] = 0.f;

        float4 hv[8], hp[8];
#pragma unroll
        for (int i = 0; i < 8; i++)
            hv[i] = __ldcg(hcur + (size_t)(kqbase + i) * BATCH + lane);

#pragma unroll
        for (int c = 0; c < 2; c++) {
            if (c < 1) {
#pragma unroll
                for (int i = 0; i < 8; i++)
                    hp[i] = __ldcg(hcur + (size_t)(kqbase + 8 + i) * BATCH + lane);
            }
#pragma unroll
            for (int i = 0; i < 8; i++) {
                int k0 = (kqbase + c * 8 + i) * 4;
                float hd[4] = {hv[i].x, hv[i].y, hv[i].z, hv[i].w};
#pragma unroll
                for (int d = 0; d < 4; d++) {
                    float4 wa = *(const float4*)&swT[k0 + d][0];
                    float4 wb = *(const float4*)&swT[k0 + d][4];
                    acc[0] += wa.x * hd[d];
                    acc[1] += wa.y * hd[d];
                    acc[2] += wa.z * hd[d];
                    acc[3] += wa.w * hd[d];
                    acc[4] += wb.x * hd[d];
                    acc[5] += wb.y * hd[d];
                    acc[6] += wb.z * hd[d];
                    acc[7] += wb.w * hd[d];
                }
            }
            if (c < 1) {
#pragma unroll
                for (int i = 0; i < 8; i++) hv[i] = hp[i];
            }
        }

        *(float4*)&red[w][lane][0] = make_float4(acc[0], acc[1], acc[2], acc[3]);
        *(float4*)&red[w][lane][4] = make_float4(acc[4], acc[5], acc[6], acc[7]);
        __syncthreads();
        if (tid < 256) {
            float s = 0.f;
#pragma unroll
            for (int ww = 0; ww < 16; ww++) s += red[ww][rb][rj];
            float v = tanhf(s + sb[rj] + xval);
            __stcg(hnxt + houtOff, v);
            yseq[(size_t)t * BATCH * HID + (size_t)rb * HID + jout] = v;
        }

        __syncthreads();
        if (tid == 0) {
            red_add_release_gpu(&g_ctr, 1);
            int target = 128 * (t + 1);
            while (ld_acquire_int(&g_ctr) < target) {
                __nanosleep(64);
            }
        }
        __syncthreads();
    }
}

// =====================================================================
// In-place log_softmax over rows of 32000. Row cached in 128 KB smem.
// =====================================================================
__global__ __launch_bounds__(256)
void logsoftmax_k(float* __restrict__ out)
{
    extern __shared__ float srow[];
    __shared__ float red[256];
    int tid = threadIdx.x;
    float4* p4 = (float4*)(out + (size_t)blockIdx.x * VOCAB);

    float m = -3.4e38f;
#pragma unroll 4
    for (int i = tid; i < VOCAB / 4; i += 256) {
        float4 v = p4[i];
        *(float4*)&srow[i * 4] = v;
        m = fmaxf(m, fmaxf(fmaxf(v.x, v.y), fmaxf(v.z, v.w)));
    }
    red[tid] = m; __syncthreads();
    for (int s = 128; s > 0; s >>= 1) {
        if (tid < s) red[tid] = fmaxf(red[tid], red[tid + s]);
        __syncthreads();
    }
    float rm = red[0]; __syncthreads();

    float sum = 0.f;
    for (int i = tid; i < VOCAB; i += 256) sum += expf(srow[i] - rm);
    red[tid] = sum; __syncthreads();
    for (int s = 128; s > 0; s >>= 1) {
        if (tid < s) red[tid] += red[tid + s];
        __syncthreads();
    }
    float lz = rm + logf(red[0]);

    for (int i = tid; i < VOCAB / 4; i += 256) {
        float4 v = *(float4*)&srow[i * 4];
        v.x -= lz; v.y -= lz; v.z -= lz; v.w -= lz;
        p4[i] = v;
    }
}

// =====================================================================
// host orchestration (graph-capturable)
// =====================================================================
extern "C" void kernel_launch(void* const* d_in, const int* in_sizes, int n_in,
                              void* d_out, int out_size)
{
    const int*   input_x = (const int*)  d_in[0];
    const float* hidden  = (const float*)d_in[1];
    const float* emb     = (const float*)d_in[2];
    const float* W_ih    = (const float*)d_in[3];
    const float* W_hh    = (const float*)d_in[4];
    const float* b_ih    = (const float*)d_in[5];
    const float* b_hh    = (const float*)d_in[6];
    const float* W_out   = (const float*)d_in[7];
    const float* b_out   = (const float*)d_in[8];
    float* out = (float*)d_out;

    float *gx, *gxw;
    cudaGetSymbolAddress((void**)&gx,  g_x);
    cudaGetSymbolAddress((void**)&gxw, g_xw);

    cudaFuncSetAttribute(logsoftmax_k,
                         cudaFuncAttributeMaxDynamicSharedMemorySize,
                         VOCAB * (int)sizeof(float));
    cudaFuncSetAttribute(gemm_split3,
                         cudaFuncAttributeMaxDynamicSharedMemorySize,
                         4 * OTILE * (int)sizeof(float));
    cudaFuncSetAttribute(gemm_tf32,
                         cudaFuncAttributeMaxDynamicSharedMemorySize,
                         6 * OTILE * (int)sizeof(float));

    const int writeHidden = (size_t)out_size >= LOGITS_ELEMS + HIDDEN_ELEMS;

    // 1) embedding gather
    embed_k<<<MROWS, 256>>>(input_x, emb, gx);

    for (int l = 0; l < 2; l++) {
        const float* Wi = W_ih + (size_t)l * HID * HID;
        const float* Wh = W_hh + (size_t)l * HID * HID;
        const float* bi = b_ih + (size_t)l * HID;
        const float* bh = b_hh + (size_t)l * HID;

        // init transposed hidden (buf 0) + reset barrier counter
        htrans_in_k<<<BATCH * HID / 256, 256>>>(hidden + (size_t)l * BATCH * HID);

        // input projection: cp.async 3-term tf32 split, single launch
        dim3 gp(MROWS / BM, HID / BN);
        gemm_split3<<<gp, 256, 4 * OTILE * (int)sizeof(float)>>>(
            gx, Wi, gxw, bi, MROWS, HID, HID);

        // persistent recurrence (exact fp32), 512 threads
        rnn_persist<<<128, 512>>>(gxw, Wh, bh, gx);

        // new_hidden[l] = y[T-1]
        if (writeHidden)
            cudaMemcpyAsync(out + LOGITS_ELEMS + (size_t)l * BATCH * HID,
                            gx + (size_t)(T_LEN - 1) * BATCH * HID,
                            (size_t)BATCH * HID * sizeof(float),
                            cudaMemcpyDeviceToDevice, 0);
    }

    // output projection (3-stage cp.async HMMA tf32, single-sync pipeline)
    dim3 go(MROWS / BM, VOCAB / BN);
    gemm_tf32<<<go, 256, 6 * OTILE * (int)sizeof(float)>>>(
        gx, W_out, out, b_out, MROWS, VOCAB, HID);

    // in-place log_softmax
    logsoftmax_k<<<MROWS, 256, VOCAB * (int)sizeof(float)>>>(out);
}